// round 2
// baseline (speedup 1.0000x reference)
#include <cuda_runtime.h>
#include <math.h>

#define T_SEQ   2048
#define DIM     2048
#define NH      16
#define NKV     4
#define HD      128
#define QKV_OUT 3072   // (16 + 2*4) * 128

// Scratch (static device allocation — no cudaMalloc allowed)
__device__ float g_qkv[T_SEQ * QKV_OUT];  // [T, 3072]
__device__ float g_att[T_SEQ * DIM];      // [T, 2048] attention output (pre O-proj)

// ---------------------------------------------------------------------------
// SGEMM: C[M,N] = A[M,K] @ B[K,N], all row-major fp32.
// 128x128 tile, BK=16, 256 threads, 8x8 register tile per thread.
// Requires M%128==0, N%128==0, K%16==0 (true for all shapes here).
// ---------------------------------------------------------------------------
__global__ __launch_bounds__(256, 2)
void sgemm128(const float* __restrict__ A, const float* __restrict__ B,
              float* __restrict__ C, int M, int N, int K)
{
    __shared__ float As[16 * 132];  // transposed A tile, padded stride
    __shared__ float Bs[16 * 128];

    const int tid = threadIdx.x;
    const int ty  = tid >> 4;      // 0..15
    const int tx  = tid & 15;      // 0..15
    const int row0 = blockIdx.y * 128;
    const int col0 = blockIdx.x * 128;

    const int arow = tid >> 2;           // 0..63
    const int acol = (tid & 3) << 2;     // 0,4,8,12
    const int brow = tid >> 5;           // 0..7
    const int bcol = (tid & 31) << 2;    // 0..124

    const float* Aptr = A + (size_t)(row0 + arow) * K + acol;
    const float* Bptr = B + (size_t)brow * N + col0 + bcol;

    float acc[8][8];
    #pragma unroll
    for (int i = 0; i < 8; i++)
        #pragma unroll
        for (int j = 0; j < 8; j++) acc[i][j] = 0.f;

    for (int k0 = 0; k0 < K; k0 += 16) {
        float4 a0 = *(const float4*)(Aptr + k0);
        float4 a1 = *(const float4*)(Aptr + (size_t)64 * K + k0);
        float4 b0 = *(const float4*)(Bptr + (size_t)k0 * N);
        float4 b1 = *(const float4*)(Bptr + (size_t)(k0 + 8) * N);

        As[(acol + 0) * 132 + arow] = a0.x;
        As[(acol + 1) * 132 + arow] = a0.y;
        As[(acol + 2) * 132 + arow] = a0.z;
        As[(acol + 3) * 132 + arow] = a0.w;
        As[(acol + 0) * 132 + arow + 64] = a1.x;
        As[(acol + 1) * 132 + arow + 64] = a1.y;
        As[(acol + 2) * 132 + arow + 64] = a1.z;
        As[(acol + 3) * 132 + arow + 64] = a1.w;
        *(float4*)&Bs[brow * 128 + bcol] = b0;
        *(float4*)&Bs[(brow + 8) * 128 + bcol] = b1;
        __syncthreads();

        #pragma unroll
        for (int kk = 0; kk < 16; kk++) {
            float a[8], b[8];
            *(float4*)&a[0] = *(const float4*)&As[kk * 132 + ty * 8];
            *(float4*)&a[4] = *(const float4*)&As[kk * 132 + ty * 8 + 4];
            *(float4*)&b[0] = *(const float4*)&Bs[kk * 128 + tx * 8];
            *(float4*)&b[4] = *(const float4*)&Bs[kk * 128 + tx * 8 + 4];
            #pragma unroll
            for (int i = 0; i < 8; i++)
                #pragma unroll
                for (int j = 0; j < 8; j++)
                    acc[i][j] = fmaf(a[i], b[j], acc[i][j]);
        }
        __syncthreads();
    }

    #pragma unroll
    for (int i = 0; i < 8; i++) {
        float* Cp = C + (size_t)(row0 + ty * 8 + i) * N + col0 + tx * 8;
        *(float4*)Cp       = make_float4(acc[i][0], acc[i][1], acc[i][2], acc[i][3]);
        *(float4*)(Cp + 4) = make_float4(acc[i][4], acc[i][5], acc[i][6], acc[i][7]);
    }
}

// ---------------------------------------------------------------------------
// Flash attention (fp32, causal, GQA). One CTA per (64-query block, head).
// 256 threads: ty = tid/16 (row group), tx = tid%16 (col group).
// S tile: rows r = ty + i*16 (i<4), cols c = tx + j*16 (j<4).
// O tile: rows r = ty + i*16 (i<4), cols c = tx + j*16 (j<8).
// Heavy (large-qb) blocks are scheduled FIRST to avoid a causal-tail wave.
// ---------------------------------------------------------------------------
__global__ __launch_bounds__(256, 1)
void attn_kernel()
{
    extern __shared__ float sm[];
    float* Qs   = sm;                 // 64 x 128            (8192)
    float* KsT  = Qs + 64 * 128;      // 128 x 65 transposed (8320)
    float* Vs   = KsT + 128 * 65;     // 64 x 128            (8192)
    float* Ps   = Vs + 64 * 128;      // 64 x 65             (4160)
    float* m_sh = Ps + 64 * 65;       // 64
    float* l_sh = m_sh + 64;          // 64
    float* a_sh = l_sh + 64;          // 64

    const int tid = threadIdx.x;
    const int qb  = (gridDim.x - 1) - blockIdx.x;  // heavy blocks first
    const int h   = blockIdx.y;          // 0..15
    const int q0  = qb << 6;
    const int qoff = h * HD;
    const int kvh  = h >> 2;             // NH/NKV = 4
    const int koff = NH * HD + kvh * HD;
    const int voff = koff + NKV * HD;

    // Load Q block (64x128), coalesced float4
    #pragma unroll
    for (int k = 0; k < 8; k++) {
        int idx = tid + k * 256;
        int r  = idx >> 5;
        int c4 = (idx & 31) << 2;
        *(float4*)&Qs[r * 128 + c4] =
            *(const float4*)&g_qkv[(size_t)(q0 + r) * QKV_OUT + qoff + c4];
    }
    if (tid < 64) { m_sh[tid] = -INFINITY; l_sh[tid] = 0.f; }

    const int ty = tid >> 4;
    const int tx = tid & 15;

    float o[4][8];
    #pragma unroll
    for (int i = 0; i < 4; i++)
        #pragma unroll
        for (int j = 0; j < 8; j++) o[i][j] = 0.f;

    for (int kb = 0; kb <= qb; kb++) {
        __syncthreads();  // Q/stats ready; prior iteration done with Ks/Vs/Ps

        // Load K (transposed into smem) and V for this key block
        const int k0row = kb << 6;
        #pragma unroll
        for (int k = 0; k < 8; k++) {
            int idx = tid + k * 256;
            int r  = idx >> 5;
            int c4 = (idx & 31) << 2;
            float4 kv = *(const float4*)&g_qkv[(size_t)(k0row + r) * QKV_OUT + koff + c4];
            KsT[(c4 + 0) * 65 + r] = kv.x;
            KsT[(c4 + 1) * 65 + r] = kv.y;
            KsT[(c4 + 2) * 65 + r] = kv.z;
            KsT[(c4 + 3) * 65 + r] = kv.w;
            *(float4*)&Vs[r * 128 + c4] =
                *(const float4*)&g_qkv[(size_t)(k0row + r) * QKV_OUT + voff + c4];
        }
        __syncthreads();

        // S = Q K^T  (64x64, 4x4 per thread)
        float s[4][4];
        #pragma unroll
        for (int i = 0; i < 4; i++)
            #pragma unroll
            for (int j = 0; j < 4; j++) s[i][j] = 0.f;

        #pragma unroll 8
        for (int d = 0; d < HD; d += 4) {
            float q[4][4];
            #pragma unroll
            for (int i = 0; i < 4; i++)
                *(float4*)q[i] = *(const float4*)&Qs[(ty + i * 16) * 128 + d];
            #pragma unroll
            for (int u = 0; u < 4; u++) {
                float kv[4];
                #pragma unroll
                for (int j = 0; j < 4; j++)
                    kv[j] = KsT[(d + u) * 65 + tx + j * 16];
                #pragma unroll
                for (int i = 0; i < 4; i++)
                    #pragma unroll
                    for (int j = 0; j < 4; j++)
                        s[i][j] = fmaf(q[i][u], kv[j], s[i][j]);
            }
        }

        const float scale = 0.088388347648318447f;  // 1/sqrt(128)
        if (kb == qb) {
            #pragma unroll
            for (int i = 0; i < 4; i++)
                #pragma unroll
                for (int j = 0; j < 4; j++)
                    s[i][j] = (tx + j * 16 > ty + i * 16) ? -INFINITY
                                                          : s[i][j] * scale;
        } else {
            #pragma unroll
            for (int i = 0; i < 4; i++)
                #pragma unroll
                for (int j = 0; j < 4; j++) s[i][j] *= scale;
        }

        // Online softmax per row (reduce over 16 tx-lanes, width-16 shuffles)
        #pragma unroll
        for (int i = 0; i < 4; i++) {
            const int r = ty + i * 16;
            float mloc = fmaxf(fmaxf(s[i][0], s[i][1]), fmaxf(s[i][2], s[i][3]));
            #pragma unroll
            for (int off = 8; off >= 1; off >>= 1)
                mloc = fmaxf(mloc, __shfl_xor_sync(0xffffffffu, mloc, off, 16));
            const float m_old = m_sh[r];
            const float m_new = fmaxf(m_old, mloc);
            float rsum = 0.f;
            #pragma unroll
            for (int j = 0; j < 4; j++) {
                float p = __expf(s[i][j] - m_new);
                s[i][j] = p;
                rsum += p;
            }
            #pragma unroll
            for (int off = 8; off >= 1; off >>= 1)
                rsum += __shfl_xor_sync(0xffffffffu, rsum, off, 16);
            if (tx == 0) {
                const float alpha = __expf(m_old - m_new);
                a_sh[r] = alpha;
                l_sh[r] = l_sh[r] * alpha + rsum;
                m_sh[r] = m_new;
            }
            #pragma unroll
            for (int j = 0; j < 4; j++)
                Ps[r * 65 + tx + j * 16] = s[i][j];
        }
        __syncthreads();

        // O = alpha * O + P @ V  (64x128, 4x8 per thread)
        float al[4];
        #pragma unroll
        for (int i = 0; i < 4; i++) al[i] = a_sh[ty + i * 16];
        #pragma unroll
        for (int i = 0; i < 4; i++)
            #pragma unroll
            for (int j = 0; j < 8; j++) o[i][j] *= al[i];

        #pragma unroll 8
        for (int kk = 0; kk < 64; kk++) {
            float p[4], v[8];
            #pragma unroll
            for (int i = 0; i < 4; i++) p[i] = Ps[(ty + i * 16) * 65 + kk];
            #pragma unroll
            for (int j = 0; j < 8; j++) v[j] = Vs[kk * 128 + tx + j * 16];
            #pragma unroll
            for (int i = 0; i < 4; i++)
                #pragma unroll
                for (int j = 0; j < 8; j++)
                    o[i][j] = fmaf(p[i], v[j], o[i][j]);
        }
    }

    // Finalize: divide by l, write to [T, NH*HD] scratch
    #pragma unroll
    for (int i = 0; i < 4; i++) {
        const int r = ty + i * 16;
        const float inv = 1.f / l_sh[r];
        float* dst = g_att + (size_t)(q0 + r) * DIM + h * HD + tx;
        #pragma unroll
        for (int j = 0; j < 8; j++)
            dst[j * 16] = o[i][j] * inv;
    }
}

// ---------------------------------------------------------------------------
extern "C" void kernel_launch(void* const* d_in, const int* in_sizes, int n_in,
                              void* d_out, int out_size)
{
    const float* x    = (const float*)d_in[0];   // [2048, 2048]
    const float* Wqkv = (const float*)d_in[1];   // [2048, 3072]
    const float* Wo   = (const float*)d_in[2];   // [2048, 2048]
    float* out = (float*)d_out;                  // [2048, 2048]

    float *qkv, *att;
    cudaGetSymbolAddress((void**)&qkv, g_qkv);
    cudaGetSymbolAddress((void**)&att, g_att);

    const int attn_smem = (64 * 128 + 128 * 65 + 64 * 128 + 64 * 65 + 192) * 4; // 116224 B
    cudaFuncSetAttribute(attn_kernel,
                         cudaFuncAttributeMaxDynamicSharedMemorySize, attn_smem);

    // 1) qkv = x @ W_qkv
    sgemm128<<<dim3(QKV_OUT / 128, T_SEQ / 128), 256>>>(x, Wqkv, qkv,
                                                        T_SEQ, QKV_OUT, DIM);
    // 2) attention (causal GQA flash) -> g_att
    attn_kernel<<<dim3(T_SEQ / 64, NH), 256, attn_smem>>>();
    // 3) out = att @ W_o
    sgemm128<<<dim3(DIM / 128, T_SEQ / 128), 256>>>(att, Wo, out,
                                                    T_SEQ, DIM, DIM);
}

// round 6
// speedup vs baseline: 1.4090x; 1.4090x over previous
#include <cuda_runtime.h>
#include <cuda_bf16.h>
#include <math.h>
#include <stdint.h>

#define T_SEQ   2048
#define DIM     2048
#define NH      16
#define NKV     4
#define HD      128
#define QKV_OUT 3072   // (16 + 2*4) * 128

// ---------------------------------------------------------------------------
// Scratch (static device allocation — no cudaMalloc allowed)
// ---------------------------------------------------------------------------
__device__ float g_qkv[T_SEQ * QKV_OUT];                  // [T, 3072] fp32
__device__ float g_att[T_SEQ * DIM];                      // [T, 2048] fp32
__device__ __nv_bfloat16 g_x_hi[T_SEQ * DIM];             // x split
__device__ __nv_bfloat16 g_x_lo[T_SEQ * DIM];
__device__ __nv_bfloat16 g_att_hi[T_SEQ * DIM];           // att split
__device__ __nv_bfloat16 g_att_lo[T_SEQ * DIM];
__device__ __nv_bfloat16 g_wqkv_hi[QKV_OUT * DIM];        // W_qkv^T [N,K] split
__device__ __nv_bfloat16 g_wqkv_lo[QKV_OUT * DIM];
__device__ __nv_bfloat16 g_wo_hi[DIM * DIM];              // W_o^T [N,K] split
__device__ __nv_bfloat16 g_wo_lo[DIM * DIM];

// ---------------------------------------------------------------------------
// PTX helpers (portable sm_80+ path: ldmatrix / mma.sync / cp.async)
// ---------------------------------------------------------------------------
__device__ __forceinline__ uint32_t smem_to_u32(const void* p) {
    uint32_t a;
    asm("{ .reg .u64 t; cvta.to.shared.u64 t, %1; cvt.u32.u64 %0, t; }"
        : "=r"(a) : "l"(p));
    return a;
}

__device__ __forceinline__ void cp_async16(uint32_t sm, const void* g) {
    asm volatile("cp.async.cg.shared.global [%0], [%1], 16;"
                 :: "r"(sm), "l"(g) : "memory");
}
#define CP_COMMIT() asm volatile("cp.async.commit_group;" ::: "memory")
#define CP_WAIT(n)  asm volatile("cp.async.wait_group %0;" :: "n"(n) : "memory")

__device__ __forceinline__ void ldm_x4(uint32_t addr, uint32_t* r) {
    asm volatile("ldmatrix.sync.aligned.m8n8.x4.shared.b16 {%0,%1,%2,%3}, [%4];"
                 : "=r"(r[0]), "=r"(r[1]), "=r"(r[2]), "=r"(r[3]) : "r"(addr));
}

// D = A(bf16)*B(bf16) + C, m16n8k16, A row-major, B col-major.
// b0 must hold (k0-7, n-octet), b1 the matching (k8-15, n-octet).
__device__ __forceinline__ void mma_bf16(float* c, const uint32_t* a,
                                         uint32_t b0, uint32_t b1) {
    asm volatile(
        "mma.sync.aligned.m16n8k16.row.col.f32.bf16.bf16.f32 "
        "{%0,%1,%2,%3}, {%4,%5,%6,%7}, {%8,%9}, {%0,%1,%2,%3};"
        : "+f"(c[0]), "+f"(c[1]), "+f"(c[2]), "+f"(c[3])
        : "r"(a[0]), "r"(a[1]), "r"(a[2]), "r"(a[3]), "r"(b0), "r"(b1));
}

// ---------------------------------------------------------------------------
// Split fp32 -> bf16 hi/lo (row-major, same layout)
// ---------------------------------------------------------------------------
__global__ void split_rm(const float* __restrict__ src,
                         __nv_bfloat16* __restrict__ hi,
                         __nv_bfloat16* __restrict__ lo, int n)
{
    int i = (blockIdx.x * blockDim.x + threadIdx.x) * 4;
    if (i >= n) return;
    float4 v = *(const float4*)(src + i);
    __nv_bfloat16 h0 = __float2bfloat16_rn(v.x);
    __nv_bfloat16 h1 = __float2bfloat16_rn(v.y);
    __nv_bfloat16 h2 = __float2bfloat16_rn(v.z);
    __nv_bfloat16 h3 = __float2bfloat16_rn(v.w);
    __nv_bfloat16 l0 = __float2bfloat16_rn(v.x - __bfloat162float(h0));
    __nv_bfloat16 l1 = __float2bfloat16_rn(v.y - __bfloat162float(h1));
    __nv_bfloat16 l2 = __float2bfloat16_rn(v.z - __bfloat162float(h2));
    __nv_bfloat16 l3 = __float2bfloat16_rn(v.w - __bfloat162float(h3));
    __nv_bfloat162* H = (__nv_bfloat162*)(hi + i);
    __nv_bfloat162* L = (__nv_bfloat162*)(lo + i);
    H[0] = __nv_bfloat162(h0, h1); H[1] = __nv_bfloat162(h2, h3);
    L[0] = __nv_bfloat162(l0, l1); L[1] = __nv_bfloat162(l2, l3);
}

// ---------------------------------------------------------------------------
// Transpose + split: W[K,N] fp32 -> T[N,K] bf16 hi/lo
// ---------------------------------------------------------------------------
__global__ void split_tr(const float* __restrict__ W,
                         __nv_bfloat16* __restrict__ Thi,
                         __nv_bfloat16* __restrict__ Tlo, int K, int N)
{
    __shared__ float t[32][33];
    const int n0 = blockIdx.x * 32;
    const int k0 = blockIdx.y * 32;
    const int tx = threadIdx.x, ty = threadIdx.y;
    #pragma unroll
    for (int i = 0; i < 4; i++)
        t[ty + i * 8][tx] = W[(size_t)(k0 + ty + i * 8) * N + n0 + tx];
    __syncthreads();
    #pragma unroll
    for (int i = 0; i < 4; i++) {
        float v = t[tx][ty + i * 8];
        __nv_bfloat16 h = __float2bfloat16_rn(v);
        __nv_bfloat16 l = __float2bfloat16_rn(v - __bfloat162float(h));
        size_t o = (size_t)(n0 + ty + i * 8) * K + k0 + tx;
        Thi[o] = h;
        Tlo[o] = l;
    }
}

// ---------------------------------------------------------------------------
// Split-bf16 tensor-core GEMM (mma.sync): C[M,N] = A[M,K] @ B[K,N],
// B given transposed as Bt[N,K]. 128x128 CTA tile, BK=32 double-buffered.
// 8 warps = 4(m) x 2(n); warp tile 32x64 = 2 m16 x 8 n8 mma tiles.
// Smem rows padded to 80B -> ldmatrix 8-lane pattern is bank-conflict-free.
// ---------------------------------------------------------------------------
#define BK        32
#define PAD_ELE   40                      // 32 bf16 + 8 pad
#define PAD_B     (PAD_ELE * 2)           // 80 bytes per row
#define TILE_B    (128 * PAD_B)           // 10240 per tile
#define STAGE_B   (4 * TILE_B)            // Ahi,Alo,Bhi,Blo = 40960
#define GSMEM     (2 * STAGE_B)           // 81920

__device__ __forceinline__ void load_tile32(uint32_t sm_tile,
                                            const __nv_bfloat16* src,
                                            int row_base, int K, int k0, int tid)
{
    // 128 rows x 64B = 512 16B units, 256 threads -> 2 each
    #pragma unroll
    for (int i = 0; i < 2; i++) {
        int u = tid + i * 256;
        int r = u >> 2;                  // row 0..127
        int c16 = (u & 3) << 4;          // 0,16,32,48
        const char* g = (const char*)(src + (size_t)(row_base + r) * K + k0) + c16;
        cp_async16(sm_tile + r * PAD_B + c16, g);
    }
}

__global__ __launch_bounds__(256, 1)
void gemm_bf16split(const __nv_bfloat16* __restrict__ Ahi,
                    const __nv_bfloat16* __restrict__ Alo,
                    const __nv_bfloat16* __restrict__ Bhi,   // [N,K]
                    const __nv_bfloat16* __restrict__ Blo,   // [N,K]
                    float* __restrict__ C, int M, int N, int K)
{
    extern __shared__ char smem[];
    const uint32_t sb = smem_to_u32(smem);
    const int tid  = threadIdx.x;
    const int wid  = tid >> 5;
    const int lane = tid & 31;
    const int wm   = wid & 3;            // 0..3  (m)
    const int wn   = wid >> 2;           // 0..1  (n)
    const int row0 = blockIdx.y * 128;
    const int col0 = blockIdx.x * 128;

    float acc[2][8][4];
    #pragma unroll
    for (int i = 0; i < 2; i++)
        #pragma unroll
        for (int j = 0; j < 8; j++)
            #pragma unroll
            for (int q = 0; q < 4; q++) acc[i][j][q] = 0.f;

    // ldmatrix addressing within a [16 rows x 32B] region at given smem base:
    // lane row = l&15, byte col = (l>=16)*16
    const int lrow = lane & 15;
    const int lcol = (lane >> 4) << 4;

    const int NC = K / BK;

    // preload stage 0
    {
        uint32_t s = sb;
        load_tile32(s,              Ahi, row0, K, 0, tid);
        load_tile32(s + TILE_B,     Alo, row0, K, 0, tid);
        load_tile32(s + 2 * TILE_B, Bhi, col0, K, 0, tid);
        load_tile32(s + 3 * TILE_B, Blo, col0, K, 0, tid);
        CP_COMMIT();
    }

    for (int c = 0; c < NC; ++c) {
        if (c + 1 < NC) {
            uint32_t s = sb + ((c + 1) & 1) * STAGE_B;
            int k0 = (c + 1) * BK;
            load_tile32(s,              Ahi, row0, K, k0, tid);
            load_tile32(s + TILE_B,     Alo, row0, K, k0, tid);
            load_tile32(s + 2 * TILE_B, Bhi, col0, K, k0, tid);
            load_tile32(s + 3 * TILE_B, Blo, col0, K, k0, tid);
            CP_COMMIT();
            CP_WAIT(1);
        } else {
            CP_WAIT(0);
        }
        __syncthreads();

        const uint32_t s = sb + (c & 1) * STAGE_B;
        const uint32_t sAhi = s;
        const uint32_t sAlo = s + TILE_B;
        const uint32_t sBhi = s + 2 * TILE_B;
        const uint32_t sBlo = s + 3 * TILE_B;

        #pragma unroll
        for (int ks = 0; ks < 2; ks++) {
            const int kb = ks * 32;       // byte offset of k16 step
            uint32_t ah[2][4], al[2][4];
            #pragma unroll
            for (int i = 0; i < 2; i++) {
                const int r = wm * 32 + i * 16 + lrow;
                ldm_x4(sAhi + r * PAD_B + kb + lcol, ah[i]);
                ldm_x4(sAlo + r * PAD_B + kb + lcol, al[i]);
            }
            // ldm_x4 over Bt rows p*16+lrow gives regs:
            //   [0]=(n0-7,k0-7) [1]=(n8-15,k0-7) [2]=(n0-7,k8-15) [3]=(n8-15,k8-15)
            uint32_t bh[4][4], bl[4][4];
            #pragma unroll
            for (int p = 0; p < 4; p++) {
                const int r = wn * 64 + p * 16 + lrow;
                ldm_x4(sBhi + r * PAD_B + kb + lcol, bh[p]);
                ldm_x4(sBlo + r * PAD_B + kb + lcol, bl[p]);
            }
            #pragma unroll
            for (int i = 0; i < 2; i++)
                #pragma unroll
                for (int j = 0; j < 8; j++) {
                    const int p = j >> 1;
                    const int q = j & 1;          // which n-octet in the 16
                    // B operand = {(k0-7, n-octet q), (k8-15, n-octet q)}
                    mma_bf16(acc[i][j], ah[i], bh[p][q], bh[p][2 + q]);
                    mma_bf16(acc[i][j], ah[i], bl[p][q], bl[p][2 + q]);
                    mma_bf16(acc[i][j], al[i], bh[p][q], bh[p][2 + q]);
                }
        }
        __syncthreads();
    }

    // Epilogue: c0,c1 -> (row = groupID, col = 2*tig), c2,c3 -> row+8
    const int gID = lane >> 2;
    const int tig = lane & 3;
    #pragma unroll
    for (int i = 0; i < 2; i++) {
        const int rbase = row0 + wm * 32 + i * 16 + gID;
        #pragma unroll
        for (int j = 0; j < 8; j++) {
            const int cc = col0 + wn * 64 + j * 8 + tig * 2;
            float* p0 = C + (size_t)rbase * N + cc;
            float* p1 = C + (size_t)(rbase + 8) * N + cc;
            p0[0] = acc[i][j][0]; p0[1] = acc[i][j][1];
            p1[0] = acc[i][j][2]; p1[1] = acc[i][j][3];
        }
    }
}

// ---------------------------------------------------------------------------
// Flash attention (fp32, causal, GQA). Unchanged from passing baseline.
// ---------------------------------------------------------------------------
__global__ __launch_bounds__(256, 1)
void attn_kernel()
{
    extern __shared__ float sm[];
    float* Qs   = sm;                 // 64 x 128
    float* KsT  = Qs + 64 * 128;      // 128 x 65 transposed
    float* Vs   = KsT + 128 * 65;     // 64 x 128
    float* Ps   = Vs + 64 * 128;      // 64 x 65
    float* m_sh = Ps + 64 * 65;
    float* l_sh = m_sh + 64;
    float* a_sh = l_sh + 64;

    const int tid = threadIdx.x;
    const int qb  = (gridDim.x - 1) - blockIdx.x;  // heavy blocks first
    const int h   = blockIdx.y;
    const int q0  = qb << 6;
    const int qoff = h * HD;
    const int kvh  = h >> 2;
    const int koff = NH * HD + kvh * HD;
    const int voff = koff + NKV * HD;

    #pragma unroll
    for (int k = 0; k < 8; k++) {
        int idx = tid + k * 256;
        int r  = idx >> 5;
        int c4 = (idx & 31) << 2;
        *(float4*)&Qs[r * 128 + c4] =
            *(const float4*)&g_qkv[(size_t)(q0 + r) * QKV_OUT + qoff + c4];
    }
    if (tid < 64) { m_sh[tid] = -INFINITY; l_sh[tid] = 0.f; }

    const int ty = tid >> 4;
    const int tx = tid & 15;

    float o[4][8];
    #pragma unroll
    for (int i = 0; i < 4; i++)
        #pragma unroll
        for (int j = 0; j < 8; j++) o[i][j] = 0.f;

    for (int kb = 0; kb <= qb; kb++) {
        __syncthreads();

        const int k0row = kb << 6;
        #pragma unroll
        for (int k = 0; k < 8; k++) {
            int idx = tid + k * 256;
            int r  = idx >> 5;
            int c4 = (idx & 31) << 2;
            float4 kv = *(const float4*)&g_qkv[(size_t)(k0row + r) * QKV_OUT + koff + c4];
            KsT[(c4 + 0) * 65 + r] = kv.x;
            KsT[(c4 + 1) * 65 + r] = kv.y;
            KsT[(c4 + 2) * 65 + r] = kv.z;
            KsT[(c4 + 3) * 65 + r] = kv.w;
            *(float4*)&Vs[r * 128 + c4] =
                *(const float4*)&g_qkv[(size_t)(k0row + r) * QKV_OUT + voff + c4];
        }
        __syncthreads();

        float s[4][4];
        #pragma unroll
        for (int i = 0; i < 4; i++)
            #pragma unroll
            for (int j = 0; j < 4; j++) s[i][j] = 0.f;

        #pragma unroll 8
        for (int d = 0; d < HD; d += 4) {
            float q[4][4];
            #pragma unroll
            for (int i = 0; i < 4; i++)
                *(float4*)q[i] = *(const float4*)&Qs[(ty + i * 16) * 128 + d];
            #pragma unroll
            for (int u = 0; u < 4; u++) {
                float kv[4];
                #pragma unroll
                for (int j = 0; j < 4; j++)
                    kv[j] = KsT[(d + u) * 65 + tx + j * 16];
                #pragma unroll
                for (int i = 0; i < 4; i++)
                    #pragma unroll
                    for (int j = 0; j < 4; j++)
                        s[i][j] = fmaf(q[i][u], kv[j], s[i][j]);
            }
        }

        const float scale = 0.088388347648318447f;  // 1/sqrt(128)
        if (kb == qb) {
            #pragma unroll
            for (int i = 0; i < 4; i++)
                #pragma unroll
                for (int j = 0; j < 4; j++)
                    s[i][j] = (tx + j * 16 > ty + i * 16) ? -INFINITY
                                                          : s[i][j] * scale;
        } else {
            #pragma unroll
            for (int i = 0; i < 4; i++)
                #pragma unroll
                for (int j = 0; j < 4; j++) s[i][j] *= scale;
        }

        #pragma unroll
        for (int i = 0; i < 4; i++) {
            const int r = ty + i * 16;
            float mloc = fmaxf(fmaxf(s[i][0], s[i][1]), fmaxf(s[i][2], s[i][3]));
            #pragma unroll
            for (int off = 8; off >= 1; off >>= 1)
                mloc = fmaxf(mloc, __shfl_xor_sync(0xffffffffu, mloc, off, 16));
            const float m_old = m_sh[r];
            const float m_new = fmaxf(m_old, mloc);
            float rsum = 0.f;
            #pragma unroll
            for (int j = 0; j < 4; j++) {
                float p = __expf(s[i][j] - m_new);
                s[i][j] = p;
                rsum += p;
            }
            #pragma unroll
            for (int off = 8; off >= 1; off >>= 1)
                rsum += __shfl_xor_sync(0xffffffffu, rsum, off, 16);
            if (tx == 0) {
                const float alpha = __expf(m_old - m_new);
                a_sh[r] = alpha;
                l_sh[r] = l_sh[r] * alpha + rsum;
                m_sh[r] = m_new;
            }
            #pragma unroll
            for (int j = 0; j < 4; j++)
                Ps[r * 65 + tx + j * 16] = s[i][j];
        }
        __syncthreads();

        float al[4];
        #pragma unroll
        for (int i = 0; i < 4; i++) al[i] = a_sh[ty + i * 16];
        #pragma unroll
        for (int i = 0; i < 4; i++)
            #pragma unroll
            for (int j = 0; j < 8; j++) o[i][j] *= al[i];

        #pragma unroll 8
        for (int kk = 0; kk < 64; kk++) {
            float p[4], v[8];
            #pragma unroll
            for (int i = 0; i < 4; i++) p[i] = Ps[(ty + i * 16) * 65 + kk];
            #pragma unroll
            for (int j = 0; j < 8; j++) v[j] = Vs[kk * 128 + tx + j * 16];
            #pragma unroll
            for (int i = 0; i < 4; i++)
                #pragma unroll
                for (int j = 0; j < 8; j++)
                    o[i][j] = fmaf(p[i], v[j], o[i][j]);
        }
    }

    #pragma unroll
    for (int i = 0; i < 4; i++) {
        const int r = ty + i * 16;
        const float inv = 1.f / l_sh[r];
        float* dst = g_att + (size_t)(q0 + r) * DIM + h * HD + tx;
        #pragma unroll
        for (int j = 0; j < 8; j++)
            dst[j * 16] = o[i][j] * inv;
    }
}

// ---------------------------------------------------------------------------
extern "C" void kernel_launch(void* const* d_in, const int* in_sizes, int n_in,
                              void* d_out, int out_size)
{
    const float* x    = (const float*)d_in[0];   // [2048, 2048]
    const float* Wqkv = (const float*)d_in[1];   // [2048, 3072]
    const float* Wo   = (const float*)d_in[2];   // [2048, 2048]
    float* out = (float*)d_out;                  // [2048, 2048]

    float *qkv, *att;
    cudaGetSymbolAddress((void**)&qkv, g_qkv);
    cudaGetSymbolAddress((void**)&att, g_att);
    __nv_bfloat16 *xh, *xl, *ah, *al, *qh, *ql, *oh, *ol;
    cudaGetSymbolAddress((void**)&xh, g_x_hi);
    cudaGetSymbolAddress((void**)&xl, g_x_lo);
    cudaGetSymbolAddress((void**)&ah, g_att_hi);
    cudaGetSymbolAddress((void**)&al, g_att_lo);
    cudaGetSymbolAddress((void**)&qh, g_wqkv_hi);
    cudaGetSymbolAddress((void**)&ql, g_wqkv_lo);
    cudaGetSymbolAddress((void**)&oh, g_wo_hi);
    cudaGetSymbolAddress((void**)&ol, g_wo_lo);

    const int attn_smem = (64 * 128 + 128 * 65 + 64 * 128 + 64 * 65 + 192) * 4;
    cudaFuncSetAttribute(attn_kernel,
                         cudaFuncAttributeMaxDynamicSharedMemorySize, attn_smem);
    cudaFuncSetAttribute(gemm_bf16split,
                         cudaFuncAttributeMaxDynamicSharedMemorySize, GSMEM);

    // Prep: split x, split+transpose weights
    split_rm<<<(T_SEQ * DIM) / 1024, 256>>>(x, xh, xl, T_SEQ * DIM);
    split_tr<<<dim3(QKV_OUT / 32, DIM / 32), dim3(32, 8)>>>(Wqkv, qh, ql, DIM, QKV_OUT);
    split_tr<<<dim3(DIM / 32, DIM / 32), dim3(32, 8)>>>(Wo, oh, ol, DIM, DIM);

    // 1) qkv = x @ W_qkv  (tensor cores)
    gemm_bf16split<<<dim3(QKV_OUT / 128, T_SEQ / 128), 256, GSMEM>>>(
        xh, xl, qh, ql, qkv, T_SEQ, QKV_OUT, DIM);

    // 2) attention (causal GQA flash) -> g_att
    attn_kernel<<<dim3(T_SEQ / 64, NH), 256, attn_smem>>>();

    // 3) out = att @ W_o (tensor cores)
    split_rm<<<(T_SEQ * DIM) / 1024, 256>>>(att, ah, al, T_SEQ * DIM);
    gemm_bf16split<<<dim3(DIM / 128, T_SEQ / 128), 256, GSMEM>>>(
        ah, al, oh, ol, out, T_SEQ, DIM, DIM);
}

// round 7
// speedup vs baseline: 2.1484x; 1.5247x over previous
#include <cuda_runtime.h>
#include <cuda_bf16.h>
#include <math.h>
#include <stdint.h>

#define T_SEQ   2048
#define DIM     2048
#define NH      16
#define NKV     4
#define HD      128
#define QKV_OUT 3072   // (16 + 2*4) * 128

// ---------------------------------------------------------------------------
// Scratch (static device allocation — no cudaMalloc allowed)
// ---------------------------------------------------------------------------
__device__ __nv_bfloat16 g_x_hi[T_SEQ * DIM];             // x split
__device__ __nv_bfloat16 g_x_lo[T_SEQ * DIM];
__device__ __nv_bfloat16 g_qkv_hi[T_SEQ * QKV_OUT];       // qkv split (gemm1 out)
__device__ __nv_bfloat16 g_qkv_lo[T_SEQ * QKV_OUT];
__device__ __nv_bfloat16 g_att_hi[T_SEQ * DIM];           // attention out split
__device__ __nv_bfloat16 g_att_lo[T_SEQ * DIM];
__device__ __nv_bfloat16 g_wqkv_hi[QKV_OUT * DIM];        // W_qkv^T [N,K] split
__device__ __nv_bfloat16 g_wqkv_lo[QKV_OUT * DIM];
__device__ __nv_bfloat16 g_wo_hi[DIM * DIM];              // W_o^T [N,K] split
__device__ __nv_bfloat16 g_wo_lo[DIM * DIM];

// ---------------------------------------------------------------------------
// PTX helpers (portable sm_80+ path: ldmatrix / mma.sync / cp.async)
// ---------------------------------------------------------------------------
__device__ __forceinline__ uint32_t smem_to_u32(const void* p) {
    uint32_t a;
    asm("{ .reg .u64 t; cvta.to.shared.u64 t, %1; cvt.u32.u64 %0, t; }"
        : "=r"(a) : "l"(p));
    return a;
}

__device__ __forceinline__ void cp_async16(uint32_t sm, const void* g) {
    asm volatile("cp.async.cg.shared.global [%0], [%1], 16;"
                 :: "r"(sm), "l"(g) : "memory");
}
#define CP_COMMIT() asm volatile("cp.async.commit_group;" ::: "memory")
#define CP_WAIT(n)  asm volatile("cp.async.wait_group %0;" :: "n"(n) : "memory")

__device__ __forceinline__ void ldm_x4(uint32_t addr, uint32_t* r) {
    asm volatile("ldmatrix.sync.aligned.m8n8.x4.shared.b16 {%0,%1,%2,%3}, [%4];"
                 : "=r"(r[0]), "=r"(r[1]), "=r"(r[2]), "=r"(r[3]) : "r"(addr));
}
__device__ __forceinline__ void ldm_x4_t(uint32_t addr, uint32_t* r) {
    asm volatile("ldmatrix.sync.aligned.m8n8.x4.trans.shared.b16 {%0,%1,%2,%3}, [%4];"
                 : "=r"(r[0]), "=r"(r[1]), "=r"(r[2]), "=r"(r[3]) : "r"(addr));
}

// D = A(bf16)*B(bf16) + C, m16n8k16, A row-major, B col-major.
__device__ __forceinline__ void mma_bf16(float* c, const uint32_t* a,
                                         uint32_t b0, uint32_t b1) {
    asm volatile(
        "mma.sync.aligned.m16n8k16.row.col.f32.bf16.bf16.f32 "
        "{%0,%1,%2,%3}, {%4,%5,%6,%7}, {%8,%9}, {%0,%1,%2,%3};"
        : "+f"(c[0]), "+f"(c[1]), "+f"(c[2]), "+f"(c[3])
        : "r"(a[0]), "r"(a[1]), "r"(a[2]), "r"(a[3]), "r"(b0), "r"(b1));
}

// ---------------------------------------------------------------------------
// Split fp32 -> bf16 hi/lo (row-major, same layout)
// ---------------------------------------------------------------------------
__global__ void split_rm(const float* __restrict__ src,
                         __nv_bfloat16* __restrict__ hi,
                         __nv_bfloat16* __restrict__ lo, int n)
{
    int i = (blockIdx.x * blockDim.x + threadIdx.x) * 4;
    if (i >= n) return;
    float4 v = *(const float4*)(src + i);
    __nv_bfloat16 h0 = __float2bfloat16_rn(v.x);
    __nv_bfloat16 h1 = __float2bfloat16_rn(v.y);
    __nv_bfloat16 h2 = __float2bfloat16_rn(v.z);
    __nv_bfloat16 h3 = __float2bfloat16_rn(v.w);
    __nv_bfloat16 l0 = __float2bfloat16_rn(v.x - __bfloat162float(h0));
    __nv_bfloat16 l1 = __float2bfloat16_rn(v.y - __bfloat162float(h1));
    __nv_bfloat16 l2 = __float2bfloat16_rn(v.z - __bfloat162float(h2));
    __nv_bfloat16 l3 = __float2bfloat16_rn(v.w - __bfloat162float(h3));
    __nv_bfloat162* H = (__nv_bfloat162*)(hi + i);
    __nv_bfloat162* L = (__nv_bfloat162*)(lo + i);
    H[0] = __nv_bfloat162(h0, h1); H[1] = __nv_bfloat162(h2, h3);
    L[0] = __nv_bfloat162(l0, l1); L[1] = __nv_bfloat162(l2, l3);
}

// ---------------------------------------------------------------------------
// Transpose + split: W[K,N] fp32 -> T[N,K] bf16 hi/lo
// ---------------------------------------------------------------------------
__global__ void split_tr(const float* __restrict__ W,
                         __nv_bfloat16* __restrict__ Thi,
                         __nv_bfloat16* __restrict__ Tlo, int K, int N)
{
    __shared__ float t[32][33];
    const int n0 = blockIdx.x * 32;
    const int k0 = blockIdx.y * 32;
    const int tx = threadIdx.x, ty = threadIdx.y;
    #pragma unroll
    for (int i = 0; i < 4; i++)
        t[ty + i * 8][tx] = W[(size_t)(k0 + ty + i * 8) * N + n0 + tx];
    __syncthreads();
    #pragma unroll
    for (int i = 0; i < 4; i++) {
        float v = t[tx][ty + i * 8];
        __nv_bfloat16 h = __float2bfloat16_rn(v);
        __nv_bfloat16 l = __float2bfloat16_rn(v - __bfloat162float(h));
        size_t o = (size_t)(n0 + ty + i * 8) * K + k0 + tx;
        Thi[o] = h;
        Tlo[o] = l;
    }
}

// ---------------------------------------------------------------------------
// Split-bf16 tensor-core GEMM: C = A @ B (B given as Bt[N,K]).
// Output either fp32 C (Chi==null) or split bf16 Chi/Clo.
// ---------------------------------------------------------------------------
#define BK        32
#define PAD_ELE   40
#define PAD_B     (PAD_ELE * 2)           // 80 bytes per row
#define TILE_B    (128 * PAD_B)           // 10240 per tile
#define STAGE_B   (4 * TILE_B)            // 40960
#define GSMEM     (2 * STAGE_B)           // 81920

__device__ __forceinline__ void load_tile32(uint32_t sm_tile,
                                            const __nv_bfloat16* src,
                                            int row_base, int K, int k0, int tid)
{
    #pragma unroll
    for (int i = 0; i < 2; i++) {
        int u = tid + i * 256;
        int r = u >> 2;
        int c16 = (u & 3) << 4;
        const char* g = (const char*)(src + (size_t)(row_base + r) * K + k0) + c16;
        cp_async16(sm_tile + r * PAD_B + c16, g);
    }
}

__global__ __launch_bounds__(256, 1)
void gemm_bf16split(const __nv_bfloat16* __restrict__ Ahi,
                    const __nv_bfloat16* __restrict__ Alo,
                    const __nv_bfloat16* __restrict__ Bhi,   // [N,K]
                    const __nv_bfloat16* __restrict__ Blo,   // [N,K]
                    float* __restrict__ C,
                    __nv_bfloat16* __restrict__ Chi,
                    __nv_bfloat16* __restrict__ Clo,
                    int M, int N, int K)
{
    extern __shared__ char smem[];
    const uint32_t sb = smem_to_u32(smem);
    const int tid  = threadIdx.x;
    const int wid  = tid >> 5;
    const int lane = tid & 31;
    const int wm   = wid & 3;
    const int wn   = wid >> 2;
    const int row0 = blockIdx.y * 128;
    const int col0 = blockIdx.x * 128;

    float acc[2][8][4];
    #pragma unroll
    for (int i = 0; i < 2; i++)
        #pragma unroll
        for (int j = 0; j < 8; j++)
            #pragma unroll
            for (int q = 0; q < 4; q++) acc[i][j][q] = 0.f;

    const int lrow = lane & 15;
    const int lcol = (lane >> 4) << 4;
    const int NC = K / BK;

    {
        uint32_t s = sb;
        load_tile32(s,              Ahi, row0, K, 0, tid);
        load_tile32(s + TILE_B,     Alo, row0, K, 0, tid);
        load_tile32(s + 2 * TILE_B, Bhi, col0, K, 0, tid);
        load_tile32(s + 3 * TILE_B, Blo, col0, K, 0, tid);
        CP_COMMIT();
    }

    for (int c = 0; c < NC; ++c) {
        if (c + 1 < NC) {
            uint32_t s = sb + ((c + 1) & 1) * STAGE_B;
            int k0 = (c + 1) * BK;
            load_tile32(s,              Ahi, row0, K, k0, tid);
            load_tile32(s + TILE_B,     Alo, row0, K, k0, tid);
            load_tile32(s + 2 * TILE_B, Bhi, col0, K, k0, tid);
            load_tile32(s + 3 * TILE_B, Blo, col0, K, k0, tid);
            CP_COMMIT();
            CP_WAIT(1);
        } else {
            CP_WAIT(0);
        }
        __syncthreads();

        const uint32_t s = sb + (c & 1) * STAGE_B;
        const uint32_t sAhi = s;
        const uint32_t sAlo = s + TILE_B;
        const uint32_t sBhi = s + 2 * TILE_B;
        const uint32_t sBlo = s + 3 * TILE_B;

        #pragma unroll
        for (int ks = 0; ks < 2; ks++) {
            const int kb = ks * 32;
            uint32_t ah[2][4], al[2][4];
            #pragma unroll
            for (int i = 0; i < 2; i++) {
                const int r = wm * 32 + i * 16 + lrow;
                ldm_x4(sAhi + r * PAD_B + kb + lcol, ah[i]);
                ldm_x4(sAlo + r * PAD_B + kb + lcol, al[i]);
            }
            uint32_t bh[4][4], bl[4][4];
            #pragma unroll
            for (int p = 0; p < 4; p++) {
                const int r = wn * 64 + p * 16 + lrow;
                ldm_x4(sBhi + r * PAD_B + kb + lcol, bh[p]);
                ldm_x4(sBlo + r * PAD_B + kb + lcol, bl[p]);
            }
            #pragma unroll
            for (int i = 0; i < 2; i++)
                #pragma unroll
                for (int j = 0; j < 8; j++) {
                    const int p = j >> 1;
                    const int q = j & 1;
                    mma_bf16(acc[i][j], ah[i], bh[p][q], bh[p][2 + q]);
                    mma_bf16(acc[i][j], ah[i], bl[p][q], bl[p][2 + q]);
                    mma_bf16(acc[i][j], al[i], bh[p][q], bh[p][2 + q]);
                }
        }
        __syncthreads();
    }

    const int gID = lane >> 2;
    const int tig = lane & 3;
    #pragma unroll
    for (int i = 0; i < 2; i++) {
        const int rbase = row0 + wm * 32 + i * 16 + gID;
        #pragma unroll
        for (int j = 0; j < 8; j++) {
            const int cc = col0 + wn * 64 + j * 8 + tig * 2;
            if (Chi) {
                #pragma unroll
                for (int half = 0; half < 2; half++) {
                    const size_t o = (size_t)(rbase + half * 8) * N + cc;
                    float v0 = acc[i][j][half * 2], v1 = acc[i][j][half * 2 + 1];
                    __nv_bfloat16 h0 = __float2bfloat16_rn(v0);
                    __nv_bfloat16 h1 = __float2bfloat16_rn(v1);
                    *(__nv_bfloat162*)(Chi + o) = __nv_bfloat162(h0, h1);
                    *(__nv_bfloat162*)(Clo + o) = __nv_bfloat162(
                        __float2bfloat16_rn(v0 - __bfloat162float(h0)),
                        __float2bfloat16_rn(v1 - __bfloat162float(h1)));
                }
            } else {
                float* p0 = C + (size_t)rbase * N + cc;
                float* p1 = C + (size_t)(rbase + 8) * N + cc;
                p0[0] = acc[i][j][0]; p0[1] = acc[i][j][1];
                p1[0] = acc[i][j][2]; p1[1] = acc[i][j][3];
            }
        }
    }
}

// ---------------------------------------------------------------------------
// Flash attention with split-bf16 mma.sync (causal, GQA).
// CTA = (64-query block, head). 256 threads = 8 warps (4 m x 2 n).
// S phase: warp -> S[wm*16..+16][wn*32..+32]; PV: warp -> O[wm*16..+16][wn*64..+64].
// ---------------------------------------------------------------------------
#define SKVB 272                    // bf16 kv/q tile row stride bytes (128+8 pad)
#define SPE  72                     // S (fp32) / P (bf16) row stride elements
#define AT_QH 0
#define AT_QL (AT_QH + 64 * SKVB)   // 17408
#define AT_KH (AT_QL + 64 * SKVB)
#define AT_KL (AT_KH + 64 * SKVB)
#define AT_VH (AT_KL + 64 * SKVB)
#define AT_VL (AT_VH + 64 * SKVB)
#define AT_S  (AT_VL + 64 * SKVB)            // fp32 64x72
#define AT_PH (AT_S + 64 * SPE * 4)          // bf16 64x72
#define AT_PL (AT_PH + 64 * SPE * 2)
#define AT_M  (AT_PL + 64 * SPE * 2)
#define AT_L  (AT_M + 256)
#define AT_A  (AT_L + 256)
#define AT_TOTAL (AT_A + 256)

// load 64x128 bf16 tile from src[T,3072] into smem (stride SKVB)
__device__ __forceinline__ void load_kv64(uint32_t dst, const __nv_bfloat16* src,
                                          int row0g, int coloff, int tid)
{
    #pragma unroll
    for (int i = 0; i < 4; i++) {
        int u = tid + i * 256;
        int r = u >> 4;
        int cu = u & 15;
        cp_async16(dst + r * SKVB + cu * 16,
                   src + (size_t)(row0g + r) * QKV_OUT + coloff + cu * 8);
    }
}

__global__ __launch_bounds__(256, 1)
void attn_kernel(const __nv_bfloat16* __restrict__ Qh_g,
                 const __nv_bfloat16* __restrict__ Ql_g)
{
    extern __shared__ char smem[];
    const uint32_t sb = smem_to_u32(smem);
    float* S_sm  = (float*)(smem + AT_S);
    float* m_sh  = (float*)(smem + AT_M);
    float* l_sh  = (float*)(smem + AT_L);
    float* a_sh  = (float*)(smem + AT_A);

    const int tid  = threadIdx.x;
    const int wid  = tid >> 5;
    const int lane = tid & 31;
    const int wm   = wid & 3;
    const int wn   = wid >> 2;
    const int lrow = lane & 15;
    const int lcol = (lane >> 4) << 4;
    const int trow = (lane & 7) + 8 * ((lane >> 3) & 1);   // for trans ldm
    const int tcol = (lane >> 4) << 4;
    const int gID  = lane >> 2;
    const int tig  = lane & 3;

    const int qb = (gridDim.x - 1) - blockIdx.x;   // heavy blocks first
    const int h  = blockIdx.y;
    const int q0 = qb << 6;
    const int qoff = h * HD;
    const int koff = NH * HD + (h >> 2) * HD;
    const int voff = koff + NKV * HD;

    // Q (both hi/lo) once
    load_kv64(sb + AT_QH, Qh_g, q0, qoff, tid);
    load_kv64(sb + AT_QL, Ql_g, q0, qoff, tid);
    CP_COMMIT();
    if (tid < 64) { m_sh[tid] = -INFINITY; l_sh[tid] = 0.f; }

    float acc_o[8][4];
    #pragma unroll
    for (int j = 0; j < 8; j++)
        #pragma unroll
        for (int q = 0; q < 4; q++) acc_o[j][q] = 0.f;

    for (int kb = 0; kb <= qb; kb++) {
        __syncthreads();   // prev iter done with K/V/P
        const int k0row = kb << 6;
        load_kv64(sb + AT_KH, Qh_g, k0row, koff, tid);
        load_kv64(sb + AT_KL, Ql_g, k0row, koff, tid);
        load_kv64(sb + AT_VH, Qh_g, k0row, voff, tid);
        load_kv64(sb + AT_VL, Ql_g, k0row, voff, tid);
        CP_COMMIT();
        CP_WAIT(0);
        __syncthreads();

        // ---- S = Q K^T (split bf16, fp32 acc) ----
        float acc_s[4][4];
        #pragma unroll
        for (int j = 0; j < 4; j++)
            #pragma unroll
            for (int q = 0; q < 4; q++) acc_s[j][q] = 0.f;

        #pragma unroll
        for (int ks = 0; ks < 8; ks++) {
            const int kbyt = ks * 32;
            uint32_t ah[4], al[4];
            const int ar = wm * 16 + lrow;
            ldm_x4(sb + AT_QH + ar * SKVB + kbyt + lcol, ah);
            ldm_x4(sb + AT_QL + ar * SKVB + kbyt + lcol, al);
            uint32_t bh[2][4], bl[2][4];
            #pragma unroll
            for (int p = 0; p < 2; p++) {
                const int br = wn * 32 + p * 16 + lrow;
                ldm_x4(sb + AT_KH + br * SKVB + kbyt + lcol, bh[p]);
                ldm_x4(sb + AT_KL + br * SKVB + kbyt + lcol, bl[p]);
            }
            #pragma unroll
            for (int j = 0; j < 4; j++) {
                const int p = j >> 1;
                const int q = j & 1;
                mma_bf16(acc_s[j], ah, bh[p][q], bh[p][2 + q]);
                mma_bf16(acc_s[j], ah, bl[p][q], bl[p][2 + q]);
                mma_bf16(acc_s[j], al, bh[p][q], bh[p][2 + q]);
            }
        }

        // store S to smem
        #pragma unroll
        for (int j = 0; j < 4; j++) {
            const int cc = wn * 32 + j * 8 + tig * 2;
            const int r0 = wm * 16 + gID;
            *(float2*)&S_sm[r0 * SPE + cc]       = make_float2(acc_s[j][0], acc_s[j][1]);
            *(float2*)&S_sm[(r0 + 8) * SPE + cc] = make_float2(acc_s[j][2], acc_s[j][3]);
        }
        __syncthreads();

        // ---- softmax: 4 threads per row, 16 cols each ----
        {
            const int r = tid >> 2;
            const int part = tid & 3;
            const float scale = 0.088388347648318447f;   // 1/sqrt(128)
            const bool diag = (kb == qb);
            float sv[16];
            const float* Srow = &S_sm[r * SPE + part * 16];
            #pragma unroll
            for (int i = 0; i < 4; i++)
                *(float4*)&sv[i * 4] = *(const float4*)&Srow[i * 4];
            float mloc = -INFINITY;
            #pragma unroll
            for (int i = 0; i < 16; i++) {
                const int c = part * 16 + i;
                sv[i] = (diag && c > r) ? -INFINITY : sv[i] * scale;
                mloc = fmaxf(mloc, sv[i]);
            }
            mloc = fmaxf(mloc, __shfl_xor_sync(0xffffffffu, mloc, 1, 4));
            mloc = fmaxf(mloc, __shfl_xor_sync(0xffffffffu, mloc, 2, 4));
            const float m_old = m_sh[r];
            const float m_new = fmaxf(m_old, mloc);
            float sum = 0.f;
            float pv[16];
            #pragma unroll
            for (int i = 0; i < 16; i++) {
                pv[i] = __expf(sv[i] - m_new);
                sum += pv[i];
            }
            sum += __shfl_xor_sync(0xffffffffu, sum, 1, 4);
            sum += __shfl_xor_sync(0xffffffffu, sum, 2, 4);
            if (part == 0) {
                const float alpha = __expf(m_old - m_new);
                a_sh[r] = alpha;
                l_sh[r] = l_sh[r] * alpha + sum;
                m_sh[r] = m_new;
            }
            __nv_bfloat162* PhRow = (__nv_bfloat162*)(smem + AT_PH) + (r * SPE + part * 16) / 2;
            __nv_bfloat162* PlRow = (__nv_bfloat162*)(smem + AT_PL) + (r * SPE + part * 16) / 2;
            #pragma unroll
            for (int i = 0; i < 8; i++) {
                __nv_bfloat16 h0 = __float2bfloat16_rn(pv[2 * i]);
                __nv_bfloat16 h1 = __float2bfloat16_rn(pv[2 * i + 1]);
                PhRow[i] = __nv_bfloat162(h0, h1);
                PlRow[i] = __nv_bfloat162(
                    __float2bfloat16_rn(pv[2 * i]     - __bfloat162float(h0)),
                    __float2bfloat16_rn(pv[2 * i + 1] - __bfloat162float(h1)));
            }
        }
        __syncthreads();

        // ---- O = alpha*O + P V (split bf16) ----
        {
            const float a0 = a_sh[wm * 16 + gID];
            const float a1 = a_sh[wm * 16 + gID + 8];
            #pragma unroll
            for (int j = 0; j < 8; j++) {
                acc_o[j][0] *= a0; acc_o[j][1] *= a0;
                acc_o[j][2] *= a1; acc_o[j][3] *= a1;
            }
            #pragma unroll
            for (int ks2 = 0; ks2 < 4; ks2++) {
                uint32_t ph[4], pl[4];
                const int ar = wm * 16 + lrow;
                ldm_x4(sb + AT_PH + ar * (SPE * 2) + ks2 * 32 + lcol, ph);
                ldm_x4(sb + AT_PL + ar * (SPE * 2) + ks2 * 32 + lcol, pl);
                #pragma unroll
                for (int g = 0; g < 4; g++) {
                    uint32_t vh[4], vl[4];
                    const uint32_t voffb = (ks2 * 16 + trow) * SKVB
                                         + wn * 128 + g * 32 + tcol;
                    ldm_x4_t(sb + AT_VH + voffb, vh);
                    ldm_x4_t(sb + AT_VL + voffb, vl);
                    #pragma unroll
                    for (int q = 0; q < 2; q++) {
                        const int j = g * 2 + q;
                        mma_bf16(acc_o[j], ph, vh[2 * q], vh[2 * q + 1]);
                        mma_bf16(acc_o[j], ph, vl[2 * q], vl[2 * q + 1]);
                        mma_bf16(acc_o[j], pl, vh[2 * q], vh[2 * q + 1]);
                    }
                }
            }
        }
    }
    __syncthreads();

    // finalize: divide by l, split to bf16 hi/lo, write g_att_hi/lo
    {
        const float il0 = 1.f / l_sh[wm * 16 + gID];
        const float il1 = 1.f / l_sh[wm * 16 + gID + 8];
        #pragma unroll
        for (int j = 0; j < 8; j++) {
            const int cc = h * HD + wn * 64 + j * 8 + tig * 2;
            #pragma unroll
            for (int half = 0; half < 2; half++) {
                const int rg = q0 + wm * 16 + gID + half * 8;
                const float inv = half ? il1 : il0;
                const float v0 = acc_o[j][half * 2] * inv;
                const float v1 = acc_o[j][half * 2 + 1] * inv;
                __nv_bfloat16 h0 = __float2bfloat16_rn(v0);
                __nv_bfloat16 h1 = __float2bfloat16_rn(v1);
                const size_t o = (size_t)rg * DIM + cc;
                *(__nv_bfloat162*)(g_att_hi + o) = __nv_bfloat162(h0, h1);
                *(__nv_bfloat162*)(g_att_lo + o) = __nv_bfloat162(
                    __float2bfloat16_rn(v0 - __bfloat162float(h0)),
                    __float2bfloat16_rn(v1 - __bfloat162float(h1)));
            }
        }
    }
}

// ---------------------------------------------------------------------------
extern "C" void kernel_launch(void* const* d_in, const int* in_sizes, int n_in,
                              void* d_out, int out_size)
{
    const float* x    = (const float*)d_in[0];   // [2048, 2048]
    const float* Wqkv = (const float*)d_in[1];   // [2048, 3072]
    const float* Wo   = (const float*)d_in[2];   // [2048, 2048]
    float* out = (float*)d_out;                  // [2048, 2048]

    __nv_bfloat16 *xh, *xl, *qvh, *qvl, *ah, *al, *wqh, *wql, *woh, *wol;
    cudaGetSymbolAddress((void**)&xh,  g_x_hi);
    cudaGetSymbolAddress((void**)&xl,  g_x_lo);
    cudaGetSymbolAddress((void**)&qvh, g_qkv_hi);
    cudaGetSymbolAddress((void**)&qvl, g_qkv_lo);
    cudaGetSymbolAddress((void**)&ah,  g_att_hi);
    cudaGetSymbolAddress((void**)&al,  g_att_lo);
    cudaGetSymbolAddress((void**)&wqh, g_wqkv_hi);
    cudaGetSymbolAddress((void**)&wql, g_wqkv_lo);
    cudaGetSymbolAddress((void**)&woh, g_wo_hi);
    cudaGetSymbolAddress((void**)&wol, g_wo_lo);

    cudaFuncSetAttribute(attn_kernel,
                         cudaFuncAttributeMaxDynamicSharedMemorySize, AT_TOTAL);
    cudaFuncSetAttribute(gemm_bf16split,
                         cudaFuncAttributeMaxDynamicSharedMemorySize, GSMEM);

    // Prep
    split_rm<<<(T_SEQ * DIM) / 1024, 256>>>(x, xh, xl, T_SEQ * DIM);
    split_tr<<<dim3(QKV_OUT / 32, DIM / 32), dim3(32, 8)>>>(Wqkv, wqh, wql, DIM, QKV_OUT);
    split_tr<<<dim3(DIM / 32, DIM / 32), dim3(32, 8)>>>(Wo, woh, wol, DIM, DIM);

    // 1) qkv = x @ W_qkv  -> split bf16 out
    gemm_bf16split<<<dim3(QKV_OUT / 128, T_SEQ / 128), 256, GSMEM>>>(
        xh, xl, wqh, wql, nullptr, qvh, qvl, T_SEQ, QKV_OUT, DIM);

    // 2) attention -> g_att_hi/lo
    attn_kernel<<<dim3(T_SEQ / 64, NH), 256, AT_TOTAL>>>(qvh, qvl);

    // 3) out = att @ W_o  -> fp32
    gemm_bf16split<<<dim3(DIM / 128, T_SEQ / 128), 256, GSMEM>>>(
        ah, al, woh, wol, out, nullptr, nullptr, T_SEQ, DIM, DIM);
}